// round 12
// baseline (speedup 1.0000x reference)
#include <cuda_runtime.h>
#include <cuda_bf16.h>

// FrequencyAdaptiveNormSimple: out = sum_w softmax(alpha)[h,w] * (x - mu_w)/max(sd_w,1e-4)
// windows (5,10,20), replicate-padded stats for t < w-1. B=32,T=2048,H=512 fp32.
// Split kernels: tiny edge kernel handles t<20; main kernel is a uniform
// cumulative-ring streamer (warmup + steady + tail) with a mild reg budget
// (launch_bounds 64,12 -> ~85 regs) to lift occupancy to 12 blocks/SM.

constexpr int Bc  = 32;
constexpr int Tc  = 2048;
constexpr int Hc  = 512;
constexpr int HCc = 64;           // threads per block
constexpr int TCc = 128;          // time chunk per block (main kernel)
constexpr int NCH = Tc / TCc;     // 16
constexpr int NHB = Hc / HCc;     // 8
static_assert(TCc % 20 == 8, "tail length assumed 8");

static __device__ __forceinline__ float rsq(float v) {
    float r;
    asm("rsqrt.approx.f32 %0, %1;" : "=f"(r) : "f"(v));
    return r;
}

// softmax over the 3 per-feature window logits
static __device__ __forceinline__ void softmax3(const float* __restrict__ alpha,
                                                int h, float& w5, float& w10, float& w20) {
    float a0 = __ldg(&alpha[h * 3 + 0]);
    float a1 = __ldg(&alpha[h * 3 + 1]);
    float a2 = __ldg(&alpha[h * 3 + 2]);
    float mx = fmaxf(a0, fmaxf(a1, a2));
    float e0 = __expf(a0 - mx), e1 = __expf(a1 - mx), e2 = __expf(a2 - mx);
    float ai = 1.0f / (e0 + e1 + e2);
    w5 = e0 * ai; w10 = e1 * ai; w20 = e2 * ai;
}

// plain znorm (edge kernel only)
template <int W>
static __device__ __forceinline__ float zc(float xv, float s, float q, float al) {
    const float c1   = 1.0f / (float)(W - 1);
    const float c2   = 1.0f / ((float)W * (float)(W - 1));
    const float invW = 1.0f / (float)W;
    float var   = q * c1 - (s * c2) * s;
    float invsd = rsq(fmaxf(var, 1e-8f));
    return (xv - s * invW) * (al * invsd);
}

// ---------------- edge kernel: outputs t = 0..19 (replicate-padded) ----------------
__global__ __launch_bounds__(HCc)
void fan_edge_kernel(const float* __restrict__ x,
                     const float* __restrict__ alpha,
                     float* __restrict__ out)
{
    const int tid = threadIdx.x;
    int blk       = blockIdx.x;
    const int hb  = blk % NHB; blk /= NHB;
    const int b   = blk;
    const int h   = hb * HCc + tid;

    const float* xp = x   + (size_t)b * Tc * Hc + h;
    float*       op = out + (size_t)b * Tc * Hc + h;

    float al5, al10, al20;
    softmax3(alpha, h, al5, al10, al20);

    float r[20], ob[20];
    #pragma unroll
    for (int t = 0; t < 20; t++) { r[t] = __ldg(&xp[t * Hc]); ob[t] = 0.0f; }

    // w = 5
    {
        float s = 0.f, q = 0.f;
        #pragma unroll
        for (int t = 0; t < 20; t++) {
            float v = r[t];
            s += v; q += v * v;
            if (t >= 5) { float l = r[t - 5]; s -= l; q -= l * l; }
            if (t == 4) {
                #pragma unroll
                for (int tp = 0; tp <= 4; tp++) ob[tp] += zc<5>(r[tp], s, q, al5);
            } else if (t > 4) {
                ob[t] += zc<5>(v, s, q, al5);
            }
        }
    }
    // w = 10
    {
        float s = 0.f, q = 0.f;
        #pragma unroll
        for (int t = 0; t < 20; t++) {
            float v = r[t];
            s += v; q += v * v;
            if (t >= 10) { float l = r[t - 10]; s -= l; q -= l * l; }
            if (t == 9) {
                #pragma unroll
                for (int tp = 0; tp <= 9; tp++) ob[tp] += zc<10>(r[tp], s, q, al10);
            } else if (t > 9) {
                ob[t] += zc<10>(v, s, q, al10);
            }
        }
    }
    // w = 20
    {
        float s = 0.f, q = 0.f;
        #pragma unroll
        for (int t = 0; t < 20; t++) { float v = r[t]; s += v; q += v * v; }
        #pragma unroll
        for (int tp = 0; tp < 20; tp++) ob[tp] += zc<20>(r[tp], s, q, al20);
    }
    #pragma unroll
    for (int t = 0; t < 20; t++) __stcs(&op[t * Hc], ob[t]);
}

// ---------------- main kernel: uniform cumulative-ring streamer ----------------
// one steady-state timestep; J literal so ring indices are compile-time.
#define STEP(J, V, OPTR) {                                            \
    float _v    = (V);                                                \
    float _l20s = rcs[(J)];                 /* cs(t-20) */            \
    float _l20q = rcq[(J)];                                           \
    float _cs   = rcs[((J) + 19) % 20] + _v;                          \
    float _cq   = fmaf(_v, _v, rcq[((J) + 19) % 20]);                 \
    rcs[(J)] = _cs; rcq[(J)] = _cq;                                   \
    float _s20 = _cs - _l20s,              _q20 = _cq - _l20q;        \
    float _s10 = _cs - rcs[((J)+10)%20],   _q10 = _cq - rcq[((J)+10)%20]; \
    float _s5  = _cs - rcs[((J)+15)%20],   _q5  = _cq - rcq[((J)+15)%20]; \
    float _t5  = _s5  * -0.2f;                                        \
    float _t10 = _s10 * -0.1f;                                        \
    float _t20 = _s20 * -0.05f;                                       \
    float _m5  = _v + _t5,  _m10 = _v + _t10, _m20 = _v + _t20;       \
    float _v5  = fmaf(_t5,  _s5,  _q5);                               \
    float _v10 = fmaf(_t10, _s10, _q10);                              \
    float _v20 = fmaf(_t20, _s20, _q20);                              \
    float _w5  = a5  * rsq(fmaxf(_v5,  4e-8f));                       \
    float _w10 = a10 * rsq(fmaxf(_v10, 9e-8f));                       \
    float _w20 = a20 * rsq(fmaxf(_v20, 19e-8f));                      \
    float _o = fmaf(_m5, _w5, fmaf(_m10, _w10, _m20 * _w20));         \
    __stcs(&(OPTR)[(J) * Hc], _o); }

__global__ __launch_bounds__(HCc, 12)
void fan_main_kernel(const float* __restrict__ x,
                     const float* __restrict__ alpha,
                     float* __restrict__ out)
{
    const int tid   = threadIdx.x;
    int blk         = blockIdx.x;
    const int chunk = blk % NCH; blk /= NCH;
    const int hb    = blk % NHB; blk /= NHB;
    const int b     = blk;
    const int h     = hb * HCc + tid;

    const float* xp = x   + (size_t)b * Tc * Hc + h;
    float*       op = out + (size_t)b * Tc * Hc + h;

    float al5, al10, al20;
    softmax3(alpha, h, al5, al10, al20);
    // steady-state weights with sqrt(W-1) folded in (var0 = (W-1)*var)
    const float a5  = al5  * 2.0f;            // sqrt(4)
    const float a10 = al10 * 3.0f;            // sqrt(9)
    const float a20 = al20 * 4.35889894354f;  // sqrt(19)

    // warmup source: 20 values ending at tbeg-1.
    // chunk 0: tbeg=20, warmup reads x[0..19]; else tbeg=t0, reads x[t0-20..t0-1].
    const int t0   = chunk * TCc;
    const int tbeg = (chunk == 0) ? 20 : t0;
    const float* ph = xp + (size_t)(tbeg - 20) * Hc;

    float rcs[20], rcq[20];      // cumulative ring
    {
        float cs = 0.f, cq = 0.f;
        #pragma unroll
        for (int i = 0; i < 20; i++) {
            float v = __ldg(&ph[i * Hc]);
            cs += v;
            cq  = fmaf(v, v, cq);
            rcs[i] = cs;
            rcq[i] = cq;
        }
    }

    const int tend = t0 + TCc;
    int tb = tbeg;

    // ---- steady state: 20-step blocks, compile-time ring indices ----
    #pragma unroll 1
    for (; tb + 20 <= tend; tb += 20) {
        const float* p = xp + (size_t)tb * Hc;
        float*       o = op + (size_t)tb * Hc;
        float xv[5];
        #pragma unroll
        for (int j = 0; j < 5; j++) xv[j] = __ldg(&p[j * Hc]);
        STEP(0, xv[0], o); STEP(1, xv[1], o); STEP(2, xv[2], o);
        STEP(3, xv[3], o); STEP(4, xv[4], o);
        #pragma unroll
        for (int j = 0; j < 5; j++) xv[j] = __ldg(&p[(j + 5) * Hc]);
        STEP(5, xv[0], o); STEP(6, xv[1], o); STEP(7, xv[2], o);
        STEP(8, xv[3], o); STEP(9, xv[4], o);
        #pragma unroll
        for (int j = 0; j < 5; j++) xv[j] = __ldg(&p[(j + 10) * Hc]);
        STEP(10, xv[0], o); STEP(11, xv[1], o); STEP(12, xv[2], o);
        STEP(13, xv[3], o); STEP(14, xv[4], o);
        #pragma unroll
        for (int j = 0; j < 5; j++) xv[j] = __ldg(&p[(j + 15) * Hc]);
        STEP(15, xv[0], o); STEP(16, xv[1], o); STEP(17, xv[2], o);
        STEP(18, xv[3], o); STEP(19, xv[4], o);
    }

    // ---- fixed 8-step tail (ring phase is 0 mod 20 here) ----
    {
        const float* p = xp + (size_t)tb * Hc;
        float*       o = op + (size_t)tb * Hc;
        float xv[4];
        #pragma unroll
        for (int j = 0; j < 4; j++) xv[j] = __ldg(&p[j * Hc]);
        STEP(0, xv[0], o); STEP(1, xv[1], o); STEP(2, xv[2], o); STEP(3, xv[3], o);
        #pragma unroll
        for (int j = 0; j < 4; j++) xv[j] = __ldg(&p[(j + 4) * Hc]);
        STEP(4, xv[0], o); STEP(5, xv[1], o); STEP(6, xv[2], o); STEP(7, xv[3], o);
    }
}

extern "C" void kernel_launch(void* const* d_in, const int* in_sizes, int n_in,
                              void* d_out, int out_size) {
    const float* x     = (const float*)d_in[0];
    const float* alpha = (const float*)d_in[1];
    float*       out   = (float*)d_out;
    fan_main_kernel<<<dim3(Bc * NHB * NCH), dim3(HCc)>>>(x, alpha, out);  // 4096 blocks
    fan_edge_kernel<<<dim3(Bc * NHB),       dim3(HCc)>>>(x, alpha, out);  // 256 blocks
}

// round 13
// speedup vs baseline: 1.1005x; 1.1005x over previous
#include <cuda_runtime.h>
#include <cuda_bf16.h>

// FrequencyAdaptiveNormSimple: out = sum_w softmax(alpha)[h,w] * (x - mu_w)/max(sd_w,1e-4)
// windows (5,10,20), replicate-padded stats for t < w-1. B=32,T=2048,H=512 fp32.
// Fused heterogeneous grid, ONE launch:
//   bid <  4096 : uniform cumulative-ring streamer (warmup + steady + tail)
//   bid >= 4096 : edge CTAs computing t = 0..19 (replicate-padded stats)
// Edge CTAs ride inside the main kernel's wave slack instead of a serial launch.

constexpr int Bc  = 32;
constexpr int Tc  = 2048;
constexpr int Hc  = 512;
constexpr int HCc = 64;           // threads per block
constexpr int TCc = 128;          // time chunk per block (main path)
constexpr int NCH = Tc / TCc;     // 16
constexpr int NHB = Hc / HCc;     // 8
constexpr int NMAIN = Bc * NHB * NCH;   // 4096 main CTAs
constexpr int NEDGE = Bc * NHB;         // 256 edge CTAs
static_assert(TCc % 20 == 8, "tail length assumed 8");

static __device__ __forceinline__ float rsq(float v) {
    float r;
    asm("rsqrt.approx.f32 %0, %1;" : "=f"(r) : "f"(v));
    return r;
}

// softmax over the 3 per-feature window logits
static __device__ __forceinline__ void softmax3(const float* __restrict__ alpha,
                                                int h, float& w5, float& w10, float& w20) {
    float a0 = __ldg(&alpha[h * 3 + 0]);
    float a1 = __ldg(&alpha[h * 3 + 1]);
    float a2 = __ldg(&alpha[h * 3 + 2]);
    float mx = fmaxf(a0, fmaxf(a1, a2));
    float e0 = __expf(a0 - mx), e1 = __expf(a1 - mx), e2 = __expf(a2 - mx);
    float ai = 1.0f / (e0 + e1 + e2);
    w5 = e0 * ai; w10 = e1 * ai; w20 = e2 * ai;
}

// plain znorm (edge path only)
template <int W>
static __device__ __forceinline__ float zc(float xv, float s, float q, float al) {
    const float c1   = 1.0f / (float)(W - 1);
    const float c2   = 1.0f / ((float)W * (float)(W - 1));
    const float invW = 1.0f / (float)W;
    float var   = q * c1 - (s * c2) * s;
    float invsd = rsq(fmaxf(var, 1e-8f));
    return (xv - s * invW) * (al * invsd);
}

// one steady-state timestep; J literal so ring indices are compile-time.
// ring slot k holds cumulative (cs, cq) of time (tb-20+k) until step k
// overwrites it with time (tb+k).
#define STEP(J, V, OPTR) {                                            \
    float _v    = (V);                                                \
    float _l20s = rcs[(J)];                 /* cs(t-20) */            \
    float _l20q = rcq[(J)];                                           \
    float _cs   = rcs[((J) + 19) % 20] + _v;                          \
    float _cq   = fmaf(_v, _v, rcq[((J) + 19) % 20]);                 \
    rcs[(J)] = _cs; rcq[(J)] = _cq;                                   \
    float _s20 = _cs - _l20s,              _q20 = _cq - _l20q;        \
    float _s10 = _cs - rcs[((J)+10)%20],   _q10 = _cq - rcq[((J)+10)%20]; \
    float _s5  = _cs - rcs[((J)+15)%20],   _q5  = _cq - rcq[((J)+15)%20]; \
    float _t5  = _s5  * -0.2f;                                        \
    float _t10 = _s10 * -0.1f;                                        \
    float _t20 = _s20 * -0.05f;                                       \
    float _m5  = _v + _t5,  _m10 = _v + _t10, _m20 = _v + _t20;       \
    float _v5  = fmaf(_t5,  _s5,  _q5);                               \
    float _v10 = fmaf(_t10, _s10, _q10);                              \
    float _v20 = fmaf(_t20, _s20, _q20);                              \
    float _w5  = a5  * rsq(fmaxf(_v5,  4e-8f));                       \
    float _w10 = a10 * rsq(fmaxf(_v10, 9e-8f));                       \
    float _w20 = a20 * rsq(fmaxf(_v20, 19e-8f));                      \
    float _o = fmaf(_m5, _w5, fmaf(_m10, _w10, _m20 * _w20));         \
    __stcs(&(OPTR)[(J) * Hc], _o); }

__global__ __launch_bounds__(HCc)
void fan_kernel(const float* __restrict__ x,
                const float* __restrict__ alpha,
                float* __restrict__ out)
{
    const int tid = threadIdx.x;

    if (blockIdx.x >= NMAIN) {
        // ---------------- edge path: outputs t = 0..19 ----------------
        int e        = blockIdx.x - NMAIN;
        const int hb = e % NHB;
        const int b  = e / NHB;
        const int h  = hb * HCc + tid;

        const float* xp = x   + (size_t)b * Tc * Hc + h;
        float*       op = out + (size_t)b * Tc * Hc + h;

        float al5, al10, al20;
        softmax3(alpha, h, al5, al10, al20);

        float r[20], ob[20];
        #pragma unroll
        for (int t = 0; t < 20; t++) { r[t] = __ldg(&xp[t * Hc]); ob[t] = 0.0f; }

        // w = 5
        {
            float s = 0.f, q = 0.f;
            #pragma unroll
            for (int t = 0; t < 20; t++) {
                float v = r[t];
                s += v; q += v * v;
                if (t >= 5) { float l = r[t - 5]; s -= l; q -= l * l; }
                if (t == 4) {
                    #pragma unroll
                    for (int tp = 0; tp <= 4; tp++) ob[tp] += zc<5>(r[tp], s, q, al5);
                } else if (t > 4) {
                    ob[t] += zc<5>(v, s, q, al5);
                }
            }
        }
        // w = 10
        {
            float s = 0.f, q = 0.f;
            #pragma unroll
            for (int t = 0; t < 20; t++) {
                float v = r[t];
                s += v; q += v * v;
                if (t >= 10) { float l = r[t - 10]; s -= l; q -= l * l; }
                if (t == 9) {
                    #pragma unroll
                    for (int tp = 0; tp <= 9; tp++) ob[tp] += zc<10>(r[tp], s, q, al10);
                } else if (t > 9) {
                    ob[t] += zc<10>(v, s, q, al10);
                }
            }
        }
        // w = 20
        {
            float s = 0.f, q = 0.f;
            #pragma unroll
            for (int t = 0; t < 20; t++) { float v = r[t]; s += v; q += v * v; }
            #pragma unroll
            for (int tp = 0; tp < 20; tp++) ob[tp] += zc<20>(r[tp], s, q, al20);
        }
        #pragma unroll
        for (int t = 0; t < 20; t++) __stcs(&op[t * Hc], ob[t]);
        return;
    }

    // ---------------- main path: uniform cumulative-ring streamer ----------------
    int blk         = blockIdx.x;
    const int chunk = blk % NCH; blk /= NCH;
    const int hb    = blk % NHB; blk /= NHB;
    const int b     = blk;
    const int h     = hb * HCc + tid;

    const float* xp = x   + (size_t)b * Tc * Hc + h;
    float*       op = out + (size_t)b * Tc * Hc + h;

    float al5, al10, al20;
    softmax3(alpha, h, al5, al10, al20);
    // steady-state weights with sqrt(W-1) folded in (var0 = (W-1)*var)
    const float a5  = al5  * 2.0f;            // sqrt(4)
    const float a10 = al10 * 3.0f;            // sqrt(9)
    const float a20 = al20 * 4.35889894354f;  // sqrt(19)

    // warmup source: 20 values ending at tbeg-1.
    // chunk 0: tbeg=20, warmup reads x[0..19]; else tbeg=t0, reads x[t0-20..t0-1].
    const int t0   = chunk * TCc;
    const int tbeg = (chunk == 0) ? 20 : t0;
    const float* ph = xp + (size_t)(tbeg - 20) * Hc;

    float rcs[20], rcq[20];      // cumulative ring
    {
        float cs = 0.f, cq = 0.f;
        #pragma unroll
        for (int i = 0; i < 20; i++) {
            float v = __ldg(&ph[i * Hc]);
            cs += v;
            cq  = fmaf(v, v, cq);
            rcs[i] = cs;
            rcq[i] = cq;
        }
    }

    const int tend = t0 + TCc;
    int tb = tbeg;

    // ---- steady state: 20-step blocks, compile-time ring indices ----
    #pragma unroll 1
    for (; tb + 20 <= tend; tb += 20) {
        const float* p = xp + (size_t)tb * Hc;
        float*       o = op + (size_t)tb * Hc;
        float xv[5];
        #pragma unroll
        for (int j = 0; j < 5; j++) xv[j] = __ldg(&p[j * Hc]);
        STEP(0, xv[0], o); STEP(1, xv[1], o); STEP(2, xv[2], o);
        STEP(3, xv[3], o); STEP(4, xv[4], o);
        #pragma unroll
        for (int j = 0; j < 5; j++) xv[j] = __ldg(&p[(j + 5) * Hc]);
        STEP(5, xv[0], o); STEP(6, xv[1], o); STEP(7, xv[2], o);
        STEP(8, xv[3], o); STEP(9, xv[4], o);
        #pragma unroll
        for (int j = 0; j < 5; j++) xv[j] = __ldg(&p[(j + 10) * Hc]);
        STEP(10, xv[0], o); STEP(11, xv[1], o); STEP(12, xv[2], o);
        STEP(13, xv[3], o); STEP(14, xv[4], o);
        #pragma unroll
        for (int j = 0; j < 5; j++) xv[j] = __ldg(&p[(j + 15) * Hc]);
        STEP(15, xv[0], o); STEP(16, xv[1], o); STEP(17, xv[2], o);
        STEP(18, xv[3], o); STEP(19, xv[4], o);
    }

    // ---- fixed 8-step tail (ring phase is 0 mod 20 here) ----
    {
        const float* p = xp + (size_t)tb * Hc;
        float*       o = op + (size_t)tb * Hc;
        float xv[4];
        #pragma unroll
        for (int j = 0; j < 4; j++) xv[j] = __ldg(&p[j * Hc]);
        STEP(0, xv[0], o); STEP(1, xv[1], o); STEP(2, xv[2], o); STEP(3, xv[3], o);
        #pragma unroll
        for (int j = 0; j < 4; j++) xv[j] = __ldg(&p[(j + 4) * Hc]);
        STEP(4, xv[0], o); STEP(5, xv[1], o); STEP(6, xv[2], o); STEP(7, xv[3], o);
    }
}

extern "C" void kernel_launch(void* const* d_in, const int* in_sizes, int n_in,
                              void* d_out, int out_size) {
    const float* x     = (const float*)d_in[0];
    const float* alpha = (const float*)d_in[1];
    float*       out   = (float*)d_out;
    fan_kernel<<<dim3(NMAIN + NEDGE), dim3(HCc)>>>(x, alpha, out);  // 4352 blocks, 1 launch
}

// round 14
// speedup vs baseline: 1.1016x; 1.0010x over previous
#include <cuda_runtime.h>
#include <cuda_bf16.h>

// FrequencyAdaptiveNormSimple: out = sum_w softmax(alpha)[h,w] * (x - mu_w)/max(sd_w,1e-4)
// windows (5,10,20), replicate-padded stats for t < w-1. B=32,T=2048,H=512 fp32.
// Cumulative ring moved to SHARED memory (float2 cs,cq per slot, per-thread
// column, compile-time slot offsets -> 3 LDS.64 + 1 STS.64 per element, zero
// address ALU). Frees ~40 registers -> ~2x occupancy for latency hiding.

constexpr int Bc  = 32;
constexpr int Tc  = 2048;
constexpr int Hc  = 512;
constexpr int HCc = 64;           // threads per block
constexpr int TCc = 128;          // time chunk per block
constexpr int NCH = Tc / TCc;     // 16
constexpr int NHB = Hc / HCc;     // 8
static_assert(TCc % 20 == 8, "tail length assumed 8");

static __device__ __forceinline__ float rsq(float v) {
    float r;
    asm("rsqrt.approx.f32 %0, %1;" : "=f"(r) : "f"(v));
    return r;
}

// edge-path znorm (t < 20), plain form
template <int W>
static __device__ __forceinline__ float zc(float xv, float s, float q, float al) {
    const float c1   = 1.0f / (float)(W - 1);
    const float c2   = 1.0f / ((float)W * (float)(W - 1));
    const float invW = 1.0f / (float)W;
    float var   = q * c1 - (s * c2) * s;
    float invsd = rsq(fmaxf(var, 1e-8f));
    return (xv - s * invW) * (al * invsd);
}

// one steady-state timestep; J literal so shared-ring offsets are immediates.
// ring slot k holds cumulative (cs, cq) of time (tb-20+k) until step k
// overwrites it with time (tb+k). Running (cs_run, cq_run) stay in registers.
#define STEP(J, V, OPTR) {                                            \
    float _v    = (V);                                                \
    float2 _l20 = ring[(J)][tid];            /* cs,cq (t-20) */       \
    float2 _l10 = ring[((J) + 10) % 20][tid];                         \
    float2 _l5  = ring[((J) + 15) % 20][tid];                         \
    float _cs   = cs_run + _v;                                        \
    float _cq   = fmaf(_v, _v, cq_run);                               \
    cs_run = _cs; cq_run = _cq;                                       \
    ring[(J)][tid] = make_float2(_cs, _cq);                           \
    float _s20 = _cs - _l20.x,  _q20 = _cq - _l20.y;                  \
    float _s10 = _cs - _l10.x,  _q10 = _cq - _l10.y;                  \
    float _s5  = _cs - _l5.x,   _q5  = _cq - _l5.y;                   \
    float _t5  = _s5  * -0.2f;                                        \
    float _t10 = _s10 * -0.1f;                                        \
    float _t20 = _s20 * -0.05f;                                       \
    float _m5  = _v + _t5,  _m10 = _v + _t10, _m20 = _v + _t20;       \
    float _v5  = fmaf(_t5,  _s5,  _q5);                               \
    float _v10 = fmaf(_t10, _s10, _q10);                              \
    float _v20 = fmaf(_t20, _s20, _q20);                              \
    float _w5  = a5  * rsq(fmaxf(_v5,  4e-8f));                       \
    float _w10 = a10 * rsq(fmaxf(_v10, 9e-8f));                       \
    float _w20 = a20 * rsq(fmaxf(_v20, 19e-8f));                      \
    float _o = fmaf(_m5, _w5, fmaf(_m10, _w10, _m20 * _w20));         \
    __stcs(&(OPTR)[(J) * Hc], _o); }

__global__ __launch_bounds__(HCc)
void fan_kernel(const float* __restrict__ x,
                const float* __restrict__ alpha,
                float* __restrict__ out)
{
    __shared__ float2 ring[20][HCc];   // cumulative (cs,cq) ring, per-thread column

    const int tid   = threadIdx.x;
    int blk         = blockIdx.x;
    const int chunk = blk % NCH; blk /= NCH;
    const int hb    = blk % NHB; blk /= NHB;
    const int b     = blk;
    const int h     = hb * HCc + tid;

    const float* xp = x   + (size_t)b * Tc * Hc + h;
    float*       op = out + (size_t)b * Tc * Hc + h;

    // per-feature softmax over 3 window weights
    float a0 = __ldg(&alpha[h * 3 + 0]);
    float a1 = __ldg(&alpha[h * 3 + 1]);
    float a2 = __ldg(&alpha[h * 3 + 2]);
    float mx = fmaxf(a0, fmaxf(a1, a2));
    float e0 = __expf(a0 - mx), e1 = __expf(a1 - mx), e2 = __expf(a2 - mx);
    float ai = 1.0f / (e0 + e1 + e2);
    const float al5 = e0 * ai, al10 = e1 * ai, al20 = e2 * ai;
    // steady-state weights with sqrt(W-1) folded in (var0 = (W-1)*var)
    const float a5  = al5  * 2.0f;            // sqrt(4)
    const float a10 = al10 * 3.0f;            // sqrt(9)
    const float a20 = al20 * 4.35889894354f;  // sqrt(19)

    const float* ph;             // warmup source: 20 values ending at tbeg-1
    int tbeg;

    if (chunk == 0) {
        // ---- t = 0..19 with replicate-padded leading stats (raw scoped ring) ----
        {
            float r[20], ob[20];
            #pragma unroll
            for (int t = 0; t < 20; t++) { r[t] = __ldg(&xp[t * Hc]); ob[t] = 0.0f; }
            // w = 5
            {
                float s = 0.f, q = 0.f;
                #pragma unroll
                for (int t = 0; t < 20; t++) {
                    float v = r[t];
                    s += v; q += v * v;
                    if (t >= 5) { float l = r[t - 5]; s -= l; q -= l * l; }
                    if (t == 4) {
                        #pragma unroll
                        for (int tp = 0; tp <= 4; tp++) ob[tp] += zc<5>(r[tp], s, q, al5);
                    } else if (t > 4) {
                        ob[t] += zc<5>(v, s, q, al5);
                    }
                }
            }
            // w = 10
            {
                float s = 0.f, q = 0.f;
                #pragma unroll
                for (int t = 0; t < 20; t++) {
                    float v = r[t];
                    s += v; q += v * v;
                    if (t >= 10) { float l = r[t - 10]; s -= l; q -= l * l; }
                    if (t == 9) {
                        #pragma unroll
                        for (int tp = 0; tp <= 9; tp++) ob[tp] += zc<10>(r[tp], s, q, al10);
                    } else if (t > 9) {
                        ob[t] += zc<10>(v, s, q, al10);
                    }
                }
            }
            // w = 20
            {
                float s = 0.f, q = 0.f;
                #pragma unroll
                for (int t = 0; t < 20; t++) { float v = r[t]; s += v; q += v * v; }
                #pragma unroll
                for (int tp = 0; tp < 20; tp++) ob[tp] += zc<20>(r[tp], s, q, al20);
            }
            #pragma unroll
            for (int t = 0; t < 20; t++) __stcs(&op[t * Hc], ob[t]);
        }
        ph   = xp;          // warmup re-reads x[0..19] (L2-hot)
        tbeg = 20;
    } else {
        const int t0 = chunk * TCc;
        ph   = xp + (size_t)(t0 - 20) * Hc;
        tbeg = t0;
    }

    // ---- warmup: build cumulative shared ring over the 20 warmup values ----
    float cs_run = 0.f, cq_run = 0.f;
    #pragma unroll
    for (int i = 0; i < 20; i++) {
        float v = __ldg(&ph[i * Hc]);
        cs_run += v;
        cq_run  = fmaf(v, v, cq_run);
        ring[i][tid] = make_float2(cs_run, cq_run);
    }

    const int tend = chunk * TCc + TCc;
    int tb = tbeg;

    // ---- steady state: 20-step blocks, immediate shared-ring offsets ----
    #pragma unroll 1
    for (; tb + 20 <= tend; tb += 20) {
        const float* p = xp + (size_t)tb * Hc;
        float*       o = op + (size_t)tb * Hc;
        float xv[5];
        #pragma unroll
        for (int j = 0; j < 5; j++) xv[j] = __ldg(&p[j * Hc]);
        STEP(0, xv[0], o); STEP(1, xv[1], o); STEP(2, xv[2], o);
        STEP(3, xv[3], o); STEP(4, xv[4], o);
        #pragma unroll
        for (int j = 0; j < 5; j++) xv[j] = __ldg(&p[(j + 5) * Hc]);
        STEP(5, xv[0], o); STEP(6, xv[1], o); STEP(7, xv[2], o);
        STEP(8, xv[3], o); STEP(9, xv[4], o);
        #pragma unroll
        for (int j = 0; j < 5; j++) xv[j] = __ldg(&p[(j + 10) * Hc]);
        STEP(10, xv[0], o); STEP(11, xv[1], o); STEP(12, xv[2], o);
        STEP(13, xv[3], o); STEP(14, xv[4], o);
        #pragma unroll
        for (int j = 0; j < 5; j++) xv[j] = __ldg(&p[(j + 15) * Hc]);
        STEP(15, xv[0], o); STEP(16, xv[1], o); STEP(17, xv[2], o);
        STEP(18, xv[3], o); STEP(19, xv[4], o);
    }

    // ---- fixed 8-step tail (ring phase is 0 mod 20 here) ----
    {
        const float* p = xp + (size_t)tb * Hc;
        float*       o = op + (size_t)tb * Hc;
        float xv[4];
        #pragma unroll
        for (int j = 0; j < 4; j++) xv[j] = __ldg(&p[j * Hc]);
        STEP(0, xv[0], o); STEP(1, xv[1], o); STEP(2, xv[2], o); STEP(3, xv[3], o);
        #pragma unroll
        for (int j = 0; j < 4; j++) xv[j] = __ldg(&p[(j + 4) * Hc]);
        STEP(4, xv[0], o); STEP(5, xv[1], o); STEP(6, xv[2], o); STEP(7, xv[3], o);
    }
}

extern "C" void kernel_launch(void* const* d_in, const int* in_sizes, int n_in,
                              void* d_out, int out_size) {
    const float* x     = (const float*)d_in[0];
    const float* alpha = (const float*)d_in[1];
    float*       out   = (float*)d_out;
    fan_kernel<<<dim3(Bc * NHB * NCH), dim3(HCc)>>>(x, alpha, out);  // 4096 blocks
}

// round 15
// speedup vs baseline: 1.1119x; 1.0094x over previous
#include <cuda_runtime.h>
#include <cuda_bf16.h>

// FrequencyAdaptiveNormSimple: out = sum_w softmax(alpha)[h,w] * (x - mu_w)/max(sd_w,1e-4)
// windows (5,10,20), replicate-padded stats for t < w-1. B=32,T=2048,H=512 fp32.
// Shared-memory cumulative ring (float2 cs,cq; per-thread column; immediate
// offsets) + TCc=256 to halve warmup/halo overhead per output element.

constexpr int Bc  = 32;
constexpr int Tc  = 2048;
constexpr int Hc  = 512;
constexpr int HCc = 64;           // threads per block
constexpr int TCc = 256;          // time chunk per block
constexpr int NCH = Tc / TCc;     // 8
constexpr int NHB = Hc / HCc;     // 8
static_assert(TCc % 20 == 16, "tail length assumed 16");

static __device__ __forceinline__ float rsq(float v) {
    float r;
    asm("rsqrt.approx.f32 %0, %1;" : "=f"(r) : "f"(v));
    return r;
}

// edge-path znorm (t < 20), plain form
template <int W>
static __device__ __forceinline__ float zc(float xv, float s, float q, float al) {
    const float c1   = 1.0f / (float)(W - 1);
    const float c2   = 1.0f / ((float)W * (float)(W - 1));
    const float invW = 1.0f / (float)W;
    float var   = q * c1 - (s * c2) * s;
    float invsd = rsq(fmaxf(var, 1e-8f));
    return (xv - s * invW) * (al * invsd);
}

// one steady-state timestep; J literal so shared-ring offsets are immediates.
// ring slot k holds cumulative (cs, cq) of time (tb-20+k) until step k
// overwrites it with time (tb+k). Running (cs_run, cq_run) stay in registers.
#define STEP(J, V, OPTR) {                                            \
    float _v    = (V);                                                \
    float2 _l20 = ring[(J)][tid];            /* cs,cq (t-20) */       \
    float2 _l10 = ring[((J) + 10) % 20][tid];                         \
    float2 _l5  = ring[((J) + 15) % 20][tid];                         \
    float _cs   = cs_run + _v;                                        \
    float _cq   = fmaf(_v, _v, cq_run);                               \
    cs_run = _cs; cq_run = _cq;                                       \
    ring[(J)][tid] = make_float2(_cs, _cq);                           \
    float _s20 = _cs - _l20.x,  _q20 = _cq - _l20.y;                  \
    float _s10 = _cs - _l10.x,  _q10 = _cq - _l10.y;                  \
    float _s5  = _cs - _l5.x,   _q5  = _cq - _l5.y;                   \
    float _t5  = _s5  * -0.2f;                                        \
    float _t10 = _s10 * -0.1f;                                        \
    float _t20 = _s20 * -0.05f;                                       \
    float _m5  = _v + _t5,  _m10 = _v + _t10, _m20 = _v + _t20;       \
    float _v5  = fmaf(_t5,  _s5,  _q5);                               \
    float _v10 = fmaf(_t10, _s10, _q10);                              \
    float _v20 = fmaf(_t20, _s20, _q20);                              \
    float _w5  = a5  * rsq(fmaxf(_v5,  4e-8f));                       \
    float _w10 = a10 * rsq(fmaxf(_v10, 9e-8f));                       \
    float _w20 = a20 * rsq(fmaxf(_v20, 19e-8f));                      \
    float _o = fmaf(_m5, _w5, fmaf(_m10, _w10, _m20 * _w20));         \
    __stcs(&(OPTR)[(J) * Hc], _o); }

// 20-step group with 5-wide load batches; base P/O at time tb
#define GROUP20(P, O) {                                               \
    float xv[5];                                                      \
    _Pragma("unroll")                                                 \
    for (int _j = 0; _j < 5; _j++) xv[_j] = __ldg(&(P)[_j * Hc]);     \
    STEP(0, xv[0], O); STEP(1, xv[1], O); STEP(2, xv[2], O);          \
    STEP(3, xv[3], O); STEP(4, xv[4], O);                             \
    _Pragma("unroll")                                                 \
    for (int _j = 0; _j < 5; _j++) xv[_j] = __ldg(&(P)[(_j + 5) * Hc]); \
    STEP(5, xv[0], O); STEP(6, xv[1], O); STEP(7, xv[2], O);          \
    STEP(8, xv[3], O); STEP(9, xv[4], O);                             \
    _Pragma("unroll")                                                 \
    for (int _j = 0; _j < 5; _j++) xv[_j] = __ldg(&(P)[(_j + 10) * Hc]); \
    STEP(10, xv[0], O); STEP(11, xv[1], O); STEP(12, xv[2], O);       \
    STEP(13, xv[3], O); STEP(14, xv[4], O);                           \
    _Pragma("unroll")                                                 \
    for (int _j = 0; _j < 5; _j++) xv[_j] = __ldg(&(P)[(_j + 15) * Hc]); \
    STEP(15, xv[0], O); STEP(16, xv[1], O); STEP(17, xv[2], O);       \
    STEP(18, xv[3], O); STEP(19, xv[4], O); }

__global__ __launch_bounds__(HCc)
void fan_kernel(const float* __restrict__ x,
                const float* __restrict__ alpha,
                float* __restrict__ out)
{
    __shared__ float2 ring[20][HCc];   // cumulative (cs,cq) ring, per-thread column

    const int tid   = threadIdx.x;
    int blk         = blockIdx.x;
    const int chunk = blk % NCH; blk /= NCH;
    const int hb    = blk % NHB; blk /= NHB;
    const int b     = blk;
    const int h     = hb * HCc + tid;

    const float* xp = x   + (size_t)b * Tc * Hc + h;
    float*       op = out + (size_t)b * Tc * Hc + h;

    // per-feature softmax over 3 window weights
    float a0 = __ldg(&alpha[h * 3 + 0]);
    float a1 = __ldg(&alpha[h * 3 + 1]);
    float a2 = __ldg(&alpha[h * 3 + 2]);
    float mx = fmaxf(a0, fmaxf(a1, a2));
    float e0 = __expf(a0 - mx), e1 = __expf(a1 - mx), e2 = __expf(a2 - mx);
    float ai = 1.0f / (e0 + e1 + e2);
    const float al5 = e0 * ai, al10 = e1 * ai, al20 = e2 * ai;
    // steady-state weights with sqrt(W-1) folded in (var0 = (W-1)*var)
    const float a5  = al5  * 2.0f;            // sqrt(4)
    const float a10 = al10 * 3.0f;            // sqrt(9)
    const float a20 = al20 * 4.35889894354f;  // sqrt(19)

    const float* ph;             // warmup source: 20 values ending at tbeg-1
    int tbeg;

    if (chunk == 0) {
        // ---- t = 0..19 with replicate-padded leading stats (raw scoped ring) ----
        {
            float r[20], ob[20];
            #pragma unroll
            for (int t = 0; t < 20; t++) { r[t] = __ldg(&xp[t * Hc]); ob[t] = 0.0f; }
            // w = 5
            {
                float s = 0.f, q = 0.f;
                #pragma unroll
                for (int t = 0; t < 20; t++) {
                    float v = r[t];
                    s += v; q += v * v;
                    if (t >= 5) { float l = r[t - 5]; s -= l; q -= l * l; }
                    if (t == 4) {
                        #pragma unroll
                        for (int tp = 0; tp <= 4; tp++) ob[tp] += zc<5>(r[tp], s, q, al5);
                    } else if (t > 4) {
                        ob[t] += zc<5>(v, s, q, al5);
                    }
                }
            }
            // w = 10
            {
                float s = 0.f, q = 0.f;
                #pragma unroll
                for (int t = 0; t < 20; t++) {
                    float v = r[t];
                    s += v; q += v * v;
                    if (t >= 10) { float l = r[t - 10]; s -= l; q -= l * l; }
                    if (t == 9) {
                        #pragma unroll
                        for (int tp = 0; tp <= 9; tp++) ob[tp] += zc<10>(r[tp], s, q, al10);
                    } else if (t > 9) {
                        ob[t] += zc<10>(v, s, q, al10);
                    }
                }
            }
            // w = 20
            {
                float s = 0.f, q = 0.f;
                #pragma unroll
                for (int t = 0; t < 20; t++) { float v = r[t]; s += v; q += v * v; }
                #pragma unroll
                for (int tp = 0; tp < 20; tp++) ob[tp] += zc<20>(r[tp], s, q, al20);
            }
            #pragma unroll
            for (int t = 0; t < 20; t++) __stcs(&op[t * Hc], ob[t]);
        }
        ph   = xp;          // warmup re-reads x[0..19] (L2-hot)
        tbeg = 20;
    } else {
        const int t0 = chunk * TCc;
        ph   = xp + (size_t)(t0 - 20) * Hc;
        tbeg = t0;
    }

    // ---- warmup: build cumulative shared ring over the 20 warmup values ----
    float cs_run = 0.f, cq_run = 0.f;
    #pragma unroll
    for (int g = 0; g < 4; g++) {
        float xv[5];
        #pragma unroll
        for (int j = 0; j < 5; j++) xv[j] = __ldg(&ph[(g * 5 + j) * Hc]);
        #pragma unroll
        for (int j = 0; j < 5; j++) {
            cs_run += xv[j];
            cq_run  = fmaf(xv[j], xv[j], cq_run);
            ring[g * 5 + j][tid] = make_float2(cs_run, cq_run);
        }
    }

    const int tend = chunk * TCc + TCc;
    int tb = tbeg;

    // ---- steady state: 20-step groups, immediate shared-ring offsets ----
    #pragma unroll 1
    for (; tb + 20 <= tend; tb += 20) {
        const float* p = xp + (size_t)tb * Hc;
        float*       o = op + (size_t)tb * Hc;
        GROUP20(p, o);
    }

    // ---- fixed 16-step tail (ring phase is 0 mod 20 here) ----
    {
        const float* p = xp + (size_t)tb * Hc;
        float*       o = op + (size_t)tb * Hc;
        float xv[4];
        #pragma unroll
        for (int j = 0; j < 4; j++) xv[j] = __ldg(&p[j * Hc]);
        STEP(0, xv[0], o); STEP(1, xv[1], o); STEP(2, xv[2], o); STEP(3, xv[3], o);
        #pragma unroll
        for (int j = 0; j < 4; j++) xv[j] = __ldg(&p[(j + 4) * Hc]);
        STEP(4, xv[0], o); STEP(5, xv[1], o); STEP(6, xv[2], o); STEP(7, xv[3], o);
        #pragma unroll
        for (int j = 0; j < 4; j++) xv[j] = __ldg(&p[(j + 8) * Hc]);
        STEP(8, xv[0], o); STEP(9, xv[1], o); STEP(10, xv[2], o); STEP(11, xv[3], o);
        #pragma unroll
        for (int j = 0; j < 4; j++) xv[j] = __ldg(&p[(j + 12) * Hc]);
        STEP(12, xv[0], o); STEP(13, xv[1], o); STEP(14, xv[2], o); STEP(15, xv[3], o);
    }
}

extern "C" void kernel_launch(void* const* d_in, const int* in_sizes, int n_in,
                              void* d_out, int out_size) {
    const float* x     = (const float*)d_in[0];
    const float* alpha = (const float*)d_in[1];
    float*       out   = (float*)d_out;
    fan_kernel<<<dim3(Bc * NHB * NCH), dim3(HCc)>>>(x, alpha, out);  // 2048 blocks
}